// round 4
// baseline (speedup 1.0000x reference)
#include <cuda_runtime.h>
#include <cuda_bf16.h>
#include <math.h>
#include <stdint.h>

// Problem-fixed shapes
#define B_ 1024
#define T_ 128
#define MX_ (B_ * T_)   // 131072 rows for input-projection GEMMs

// Inter-layer activation buffers + input-projection scratch (allocation-free).
__device__ float g_buf1[MX_ * 128];      // layer1 out [B,T,128]
__device__ float g_buf2[MX_ * 64];       // layer2 out [B,T,64]
__device__ float g_buf3[B_ * 32];        // layer3 out [B,32]
__device__ float g_xzf[MX_ * 256];       // fwd input projection (max 4U=256)
__device__ float g_xzb[MX_ * 256];       // bwd input projection

__device__ __forceinline__ float sigf(float x) {
    return __fdividef(1.0f, 1.0f + __expf(-x));
}
__device__ __forceinline__ float tanhf_fast(float x) {
    return __fdividef(2.0f, 1.0f + __expf(-2.0f * x)) - 1.0f;
}

// ---------------------------------------------------------------------------
// Split-bf16 GEMM on tensor cores: C[MX, NGL] = X[MX, K] @ W[K, NGL] in ~fp32
// accuracy via 3-term bf16 split (hi*hi + hi*lo + lo*hi). mma.sync m16n8k16.
// Block: 128 thr (4 warps), tile M=64 (16/warp) x N=64. grid=(MX/64, NGL/64, 2dir)
// ---------------------------------------------------------------------------
__device__ __forceinline__ uint32_t pack_split(float v0, float v1, uint32_t& lo) {
    __nv_bfloat16 h0 = __float2bfloat16(v0);
    __nv_bfloat16 h1 = __float2bfloat16(v1);
    float r0 = v0 - __bfloat162float(h0);
    float r1 = v1 - __bfloat162float(h1);
    __nv_bfloat16 l0 = __float2bfloat16(r0);
    __nv_bfloat16 l1 = __float2bfloat16(r1);
    lo = ((uint32_t)__bfloat16_as_ushort(l1) << 16) | (uint32_t)__bfloat16_as_ushort(l0);
    return ((uint32_t)__bfloat16_as_ushort(h1) << 16) | (uint32_t)__bfloat16_as_ushort(h0);
}

__device__ __forceinline__ void mma_bf16(float* c, const uint32_t* a, uint32_t b0, uint32_t b1) {
    asm volatile(
        "mma.sync.aligned.m16n8k16.row.col.f32.bf16.bf16.f32 "
        "{%0,%1,%2,%3}, {%4,%5,%6,%7}, {%8,%9}, {%0,%1,%2,%3};\n"
        : "+f"(c[0]), "+f"(c[1]), "+f"(c[2]), "+f"(c[3])
        : "r"(a[0]), "r"(a[1]), "r"(a[2]), "r"(a[3]), "r"(b0), "r"(b1));
}

template <int K, int KP, int NGL>
__global__ void __launch_bounds__(128) inproj_gemm(
    const float* __restrict__ X,     // [MX, K]
    const float* __restrict__ Wf,    // [K, NGL]
    const float* __restrict__ Wb,
    float* __restrict__ outf,        // [MX, NGL]
    float* __restrict__ outb)
{
    constexpr int AS_STRIDE = KP + 4;     // bank-spread fp32 A tile
    constexpr int NPAIR = KP / 2;
    constexpr int WS = 65;                // padded u32 stride for W pairs

    extern __shared__ float smraw[];
    float* As = smraw;                                   // 64 * AS_STRIDE
    uint32_t* Whi = (uint32_t*)(As + 64 * AS_STRIDE);    // NPAIR * WS
    uint32_t* Wlo = Whi + NPAIR * WS;

    const float* W = blockIdx.z ? Wb : Wf;
    float* out = blockIdx.z ? outb : outf;
    const int m0 = blockIdx.x * 64;
    const int n0 = blockIdx.y * 64;
    const int tid = threadIdx.x;

    // Stage A tile fp32, zero-padding K..KP
    for (int i = tid; i < 64 * KP; i += 128) {
        int r = i / KP, c = i % KP;
        As[r * AS_STRIDE + c] = (c < K) ? X[(size_t)(m0 + r) * K + c] : 0.0f;
    }
    // Stage W tile, split hi/lo bf16, packed (even-k low, odd-k high) = B-frag format
    for (int i = tid; i < NPAIR * 64; i += 128) {
        int mp = i / 64, n = i % 64;
        int k0 = 2 * mp, k1 = 2 * mp + 1;
        float w0 = (k0 < K) ? W[(size_t)k0 * NGL + n0 + n] : 0.0f;
        float w1 = (k1 < K) ? W[(size_t)k1 * NGL + n0 + n] : 0.0f;
        uint32_t lo;
        uint32_t hi = pack_split(w0, w1, lo);
        Whi[mp * WS + n] = hi;
        Wlo[mp * WS + n] = lo;
    }
    __syncthreads();

    const int wid = tid >> 5, lane = tid & 31;
    const int g = lane >> 2, i4 = lane & 3;
    const int mrow = wid * 16;

    float acc[8][4];
#pragma unroll
    for (int nt = 0; nt < 8; ++nt)
#pragma unroll
        for (int q = 0; q < 4; ++q) acc[nt][q] = 0.0f;

#pragma unroll
    for (int kc = 0; kc < KP / 16; ++kc) {
        uint32_t ahi[4], alo[4];
#pragma unroll
        for (int fi = 0; fi < 4; ++fi) {
            int r = mrow + g + (fi & 1) * 8;
            int kk = kc * 16 + 2 * i4 + (fi >> 1) * 8;
            float v0 = As[r * AS_STRIDE + kk];
            float v1 = As[r * AS_STRIDE + kk + 1];
            ahi[fi] = pack_split(v0, v1, alo[fi]);
        }
#pragma unroll
        for (int nt = 0; nt < 8; ++nt) {
            int nn = nt * 8 + g;
            uint32_t bh0 = Whi[(kc * 8 + i4) * WS + nn];
            uint32_t bh1 = Whi[(kc * 8 + 4 + i4) * WS + nn];
            uint32_t bl0 = Wlo[(kc * 8 + i4) * WS + nn];
            uint32_t bl1 = Wlo[(kc * 8 + 4 + i4) * WS + nn];
            mma_bf16(acc[nt], ahi, bh0, bh1);   // hi*hi
            mma_bf16(acc[nt], ahi, bl0, bl1);   // hi*lo
            mma_bf16(acc[nt], alo, bh0, bh1);   // lo*hi
        }
    }

    // Write out (natural [MX, NGL] layout)
#pragma unroll
    for (int nt = 0; nt < 8; ++nt) {
        int n = n0 + nt * 8 + 2 * i4;
        size_t r = (size_t)(m0 + mrow + g);
        *(float2*)&out[r * NGL + n]       = make_float2(acc[nt][0], acc[nt][1]);
        *(float2*)&out[(r + 8) * NGL + n] = make_float2(acc[nt][2], acc[nt][3]);
    }
}

// ---------------------------------------------------------------------------
// Recurrent kernel: consumes precomputed xz (i-gate preacts), only does h@Wr.
// grid = (B/ROWS, 2 dirs), block = (ROWS/R)*U threads. Thread (rg,u) owns unit
// u for R batch rows. Wr in SMEM gate-interleaved [u2][u][{i,f,g,o}]; h double-
// buffered in SMEM (1 sync/step); next-step xz prefetched into registers.
// ---------------------------------------------------------------------------
template <int U, int ROWS, int R, bool SEQ>
__global__ void __launch_bounds__((ROWS / R) * U) lstm_rec_kernel(
    const float* __restrict__ xzf, const float* __restrict__ xzb,  // [MX, 4U]
    const float* __restrict__ Wrf, const float* __restrict__ bf,
    const float* __restrict__ Wrb, const float* __restrict__ bb,
    float* __restrict__ out)         // SEQ: [B, T, 2U]  else: [B, 2U]
{
    constexpr int G4 = 4 * U;
    constexpr int NT = (ROWS / R) * U;
    constexpr int HS = ROWS * U;

    extern __shared__ float sm[];
    float* Wr_s = sm;                 // U * G4
    float* b_s  = Wr_s + U * G4;      // G4
    float* hs0  = b_s + G4;           // HS
    float* hs1  = hs0 + HS;           // HS

    const int dir = blockIdx.y;
    const float* Wr   = dir ? Wrb : Wrf;
    const float* bias = dir ? bb  : bf;
    const float* xz   = dir ? xzb : xzf;

    const int tid = threadIdx.x;

    for (int i = tid; i < U * G4; i += NT) {
        int u2 = i / G4, c = i % G4, u = c >> 2, gg = c & 3;
        Wr_s[i] = Wr[u2 * G4 + gg * U + u];
    }
    for (int i = tid; i < G4; i += NT) b_s[i] = bias[(i & 3) * U + (i >> 2)];
    for (int i = tid; i < HS; i += NT) { hs0[i] = 0.0f; hs1[i] = 0.0f; }

    const int rg = tid / U;
    const int u  = tid % U;
    const int r0 = rg * R;
    const int b0 = blockIdx.x * ROWS;

    float c_st[R], hval[R];
#pragma unroll
    for (int j = 0; j < R; ++j) { c_st[j] = 0.0f; hval[j] = 0.0f; }

    // current-step xz values (i,f,g,o at unit u) per row
    float cx[R][4];
    {
        const int t0 = dir ? (T_ - 1) : 0;
#pragma unroll
        for (int j = 0; j < R; ++j) {
            size_t base = ((size_t)(b0 + r0 + j) * T_ + t0) * G4;
#pragma unroll
            for (int gg = 0; gg < 4; ++gg) cx[j][gg] = xz[base + gg * U + u];
        }
    }
    __syncthreads();

    const float4 bv = ((const float4*)b_s)[u];
    const float4* __restrict__ wr4 = (const float4*)Wr_s;

    float* hs_c = hs0; float* hs_n = hs1;

    for (int s = 0; s < T_; ++s) {
        const int t  = dir ? (T_ - 1 - s) : s;
        const int sn = (s + 1 < T_) ? (s + 1) : s;
        const int tn = dir ? (T_ - 1 - sn) : sn;

        // Prefetch next step's xz (overlaps the FFMA loop below).
        float pre[R][4];
#pragma unroll
        for (int j = 0; j < R; ++j) {
            size_t base = ((size_t)(b0 + r0 + j) * T_ + tn) * G4;
#pragma unroll
            for (int gg = 0; gg < 4; ++gg) pre[j][gg] = xz[base + gg * U + u];
        }

        float ai[R], afv[R], ag[R], ao[R];
#pragma unroll
        for (int j = 0; j < R; ++j) {
            ai[j]  = bv.x + cx[j][0];
            afv[j] = bv.y + cx[j][1];
            ag[j]  = bv.z + cx[j][2];
            ao[j]  = bv.w + cx[j][3];
        }

        // Recurrent projection: h @ Wr
#pragma unroll 4
        for (int u4 = 0; u4 < U / 4; ++u4) {
            float4 hv[R];
#pragma unroll
            for (int j = 0; j < R; ++j)
                hv[j] = *(const float4*)(hs_c + (r0 + j) * U + u4 * 4);
#pragma unroll
            for (int q = 0; q < 4; ++q) {
                float4 w = wr4[(u4 * 4 + q) * U + u];
#pragma unroll
                for (int j = 0; j < R; ++j) {
                    float v = (&hv[j].x)[q];
                    ai[j] += v * w.x; afv[j] += v * w.y; ag[j] += v * w.z; ao[j] += v * w.w;
                }
            }
        }

#pragma unroll
        for (int j = 0; j < R; ++j) {
            float ig = sigf(ai[j]);
            float fg = sigf(afv[j]);
            float gg = tanhf_fast(ag[j]);
            float og = sigf(ao[j]);
            c_st[j] = fg * c_st[j] + ig * gg;
            hval[j] = og * tanhf_fast(c_st[j]);
            hs_n[(r0 + j) * U + u] = hval[j];
            if (SEQ)
                out[((size_t)(b0 + r0 + j) * T_ + t) * (2 * U) + dir * U + u] = hval[j];
#pragma unroll
            for (int gg2 = 0; gg2 < 4; ++gg2) cx[j][gg2] = pre[j][gg2];
        }

        __syncthreads();
        float* tmp = hs_c; hs_c = hs_n; hs_n = tmp;
    }

    if (!SEQ) {
#pragma unroll
        for (int j = 0; j < R; ++j)
            out[(b0 + r0 + j) * (2 * U) + dir * U + u] = hval[j];
    }
}

// Final MLP head: relu(h @ d3_w + d3_b) @ cls_w + cls_b -> sigmoid. h: [B,32]
__global__ void head_kernel(const float* __restrict__ h3,
                            const float* __restrict__ d3w, const float* __restrict__ d3b,
                            const float* __restrict__ cw,  const float* __restrict__ cb,
                            float* __restrict__ out)
{
    int b = blockIdx.x * blockDim.x + threadIdx.x;
    if (b >= B_) return;

    float hv[32];
#pragma unroll
    for (int i = 0; i < 32; ++i) hv[i] = h3[b * 32 + i];

    float d[8];
#pragma unroll
    for (int j = 0; j < 8; ++j) {
        float a = d3b[j];
#pragma unroll
        for (int i = 0; i < 32; ++i) a += hv[i] * d3w[i * 8 + j];
        d[j] = a > 0.0f ? a : 0.0f;
    }
#pragma unroll
    for (int k = 0; k < 3; ++k) {
        float a = cb[k];
#pragma unroll
        for (int j = 0; j < 8; ++j) a += d[j] * cw[j * 3 + k];
        out[b * 3 + k] = 1.0f / (1.0f + expf(-a));
    }
}

static inline size_t gemm_smem(int KP) {
    int as_stride = KP + 4;
    int npair = KP / 2;
    return (size_t)(64 * as_stride) * 4 + (size_t)npair * 65 * 4 * 2;
}
static inline size_t rec_smem(int U, int ROWS) {
    return (size_t)(U * 4 * U + 4 * U + 2 * ROWS * U) * sizeof(float);
}

extern "C" void kernel_launch(void* const* d_in, const int* in_sizes, int n_in,
                              void* d_out, int out_size)
{
    const float* x     = (const float*)d_in[0];
    const float* w1f_k = (const float*)d_in[1];
    const float* w1f_r = (const float*)d_in[2];
    const float* w1f_b = (const float*)d_in[3];
    const float* w1b_k = (const float*)d_in[4];
    const float* w1b_r = (const float*)d_in[5];
    const float* w1b_b = (const float*)d_in[6];
    const float* w2f_k = (const float*)d_in[7];
    const float* w2f_r = (const float*)d_in[8];
    const float* w2f_b = (const float*)d_in[9];
    const float* w2b_k = (const float*)d_in[10];
    const float* w2b_r = (const float*)d_in[11];
    const float* w2b_b = (const float*)d_in[12];
    const float* w3f_k = (const float*)d_in[13];
    const float* w3f_r = (const float*)d_in[14];
    const float* w3f_b = (const float*)d_in[15];
    const float* w3b_k = (const float*)d_in[16];
    const float* w3b_r = (const float*)d_in[17];
    const float* w3b_b = (const float*)d_in[18];
    const float* d3_w  = (const float*)d_in[19];
    const float* d3_b  = (const float*)d_in[20];
    const float* cls_w = (const float*)d_in[21];
    const float* cls_b = (const float*)d_in[22];

    float *b1, *b2, *b3, *xzf, *xzb;
    cudaGetSymbolAddress((void**)&b1, g_buf1);
    cudaGetSymbolAddress((void**)&b2, g_buf2);
    cudaGetSymbolAddress((void**)&b3, g_buf3);
    cudaGetSymbolAddress((void**)&xzf, g_xzf);
    cudaGetSymbolAddress((void**)&xzb, g_xzb);

    const size_t gs1 = gemm_smem(80);    // K=78
    const size_t gs2 = gemm_smem(128);
    const size_t gs3 = gemm_smem(64);
    const size_t rs1 = rec_smem(64, 16); // ~73 KB
    const size_t rs2 = rec_smem(32, 16);
    const size_t rs3 = rec_smem(16, 16);

    cudaFuncSetAttribute((const void*)inproj_gemm<78, 80, 256>,
                         cudaFuncAttributeMaxDynamicSharedMemorySize, (int)gs1);
    cudaFuncSetAttribute((const void*)inproj_gemm<128, 128, 128>,
                         cudaFuncAttributeMaxDynamicSharedMemorySize, (int)gs2);
    cudaFuncSetAttribute((const void*)inproj_gemm<64, 64, 64>,
                         cudaFuncAttributeMaxDynamicSharedMemorySize, (int)gs3);
    cudaFuncSetAttribute((const void*)lstm_rec_kernel<64, 16, 4, true>,
                         cudaFuncAttributeMaxDynamicSharedMemorySize, (int)rs1);
    cudaFuncSetAttribute((const void*)lstm_rec_kernel<32, 16, 2, true>,
                         cudaFuncAttributeMaxDynamicSharedMemorySize, (int)rs2);
    cudaFuncSetAttribute((const void*)lstm_rec_kernel<16, 16, 2, false>,
                         cudaFuncAttributeMaxDynamicSharedMemorySize, (int)rs3);

    // ---- Layer 1 ----
    inproj_gemm<78, 80, 256><<<dim3(MX_ / 64, 256 / 64, 2), 128, gs1>>>(
        x, w1f_k, w1b_k, xzf, xzb);
    lstm_rec_kernel<64, 16, 4, true><<<dim3(B_ / 16, 2), 256, rs1>>>(
        xzf, xzb, w1f_r, w1f_b, w1b_r, w1b_b, b1);

    // ---- Layer 2 ----
    inproj_gemm<128, 128, 128><<<dim3(MX_ / 64, 128 / 64, 2), 128, gs2>>>(
        b1, w2f_k, w2b_k, xzf, xzb);
    lstm_rec_kernel<32, 16, 2, true><<<dim3(B_ / 16, 2), 256, rs2>>>(
        xzf, xzb, w2f_r, w2f_b, w2b_r, w2b_b, b2);

    // ---- Layer 3 ----
    inproj_gemm<64, 64, 64><<<dim3(MX_ / 64, 64 / 64, 2), 128, gs3>>>(
        b2, w3f_k, w3b_k, xzf, xzb);
    lstm_rec_kernel<16, 16, 2, false><<<dim3(B_ / 16, 2), 128, rs3>>>(
        xzf, xzb, w3f_r, w3f_b, w3b_r, w3b_b, b3);

    // ---- Head ----
    head_kernel<<<(B_ + 255) / 256, 256>>>(b3, d3_w, d3_b, cls_w, cls_b, (float*)d_out);
}